// round 2
// baseline (speedup 1.0000x reference)
#include <cuda_runtime.h>

// ---------------------------------------------------------------------------
// Problem constants
// ---------------------------------------------------------------------------
#define BATCH    131072
#define RES_DIM  100
#define NCH      6
#define CF_K     0.02f
#define TILE_B   64
#define THREADS  256

// ---------------------------------------------------------------------------
// Shared memory layout (float offsets). All offsets multiple of 4 floats (16B).
// ---------------------------------------------------------------------------
#define OFF_W1   0            // 100*128 = 12800
#define OFF_B1   12800        // 128
#define OFF_W2   12928        // 128*64 = 8192
#define OFF_B2   21120        // 64
#define OFF_W3   21184        // 64*32 = 2048
#define OFF_B3   23232        // 32
#define OFF_W4   23264        // 32
#define OFF_RES  23296        // 64*100 = 6400
#define OFF_H1   29696        // 64*132 = 8448   (stride 132: 4*132 % 32 = 16 -> no bank conflict)
#define OFF_H2   38144        // 64*68  = 4352   (stride 68:  4*68  % 32 = 16)
#define OFF_H3   42496        // 64*36  = 2304
#define SMEM_FLOATS 44800
#define SMEM_BYTES  (SMEM_FLOATS * 4)   // 179200 bytes

__device__ __forceinline__ float sigmoidf_fast(float x) {
    return 1.0f / (1.0f + __expf(-x));
}
__device__ __forceinline__ float siluf(float x) {
    return x * sigmoidf_fast(x);
}

__device__ __forceinline__ void copy_f4(float* dst, const float* src, int n_floats, int tid) {
    const float4* s4 = (const float4*)src;
    float4* d4 = (float4*)dst;
    int n4 = n_floats >> 2;
    for (int i = tid; i < n4; i += THREADS) d4[i] = s4[i];
}

// ---------------------------------------------------------------------------
// Kernel 1: per (chamber, 64-row tile) MLP -> raw[b*6 + c]
// ---------------------------------------------------------------------------
__global__ __launch_bounds__(THREADS, 1)
void chambers_mlp_kernel(const float* __restrict__ res,
                         const float* __restrict__ W1, const float* __restrict__ b1,
                         const float* __restrict__ W2, const float* __restrict__ b2,
                         const float* __restrict__ W3, const float* __restrict__ b3,
                         const float* __restrict__ W4, const float* __restrict__ b4,
                         float* __restrict__ rawOut)
{
    extern __shared__ float s[];
    const int c   = blockIdx.y;
    const int b0  = blockIdx.x * TILE_B;
    const int tid = threadIdx.x;

    // ---- stage weights + res tile into SMEM -------------------------------
    copy_f4(s + OFF_W1,  W1 + c * 12800, 12800, tid);
    copy_f4(s + OFF_B1,  b1 + c * 128,   128,   tid);
    copy_f4(s + OFF_W2,  W2 + c * 8192,  8192,  tid);
    copy_f4(s + OFF_B2,  b2 + c * 64,    64,    tid);
    copy_f4(s + OFF_W3,  W3 + c * 2048,  2048,  tid);
    copy_f4(s + OFF_B3,  b3 + c * 32,    32,    tid);
    copy_f4(s + OFF_W4,  W4 + c * 32,    32,    tid);
    copy_f4(s + OFF_RES, res + (size_t)b0 * RES_DIM, TILE_B * RES_DIM, tid);
    __syncthreads();

    // ---- Layer 1: 64x128 = res(64x100) @ W1(100x128), silu ----------------
    // thread map: rg = tid>>5 (8 groups x 8 rows), cg = tid&31 (32 groups x 4 cols)
    // warp lanes share rg -> activation loads are pure broadcast.
    {
        const int cg = tid & 31;
        const int rg = tid >> 5;
        float acc[8][4];
        #pragma unroll
        for (int i = 0; i < 8; i++)
            #pragma unroll
            for (int j = 0; j < 4; j++) acc[i][j] = 0.0f;

        const float* wbase = s + OFF_W1 + cg * 4;
        const float* abase = s + OFF_RES + rg * 8 * RES_DIM;

        #pragma unroll 2
        for (int k = 0; k < RES_DIM; k++) {
            float4 w = *(const float4*)(wbase + k * 128);
            #pragma unroll
            for (int i = 0; i < 8; i++) {
                float a = abase[i * RES_DIM + k];
                acc[i][0] = fmaf(a, w.x, acc[i][0]);
                acc[i][1] = fmaf(a, w.y, acc[i][1]);
                acc[i][2] = fmaf(a, w.z, acc[i][2]);
                acc[i][3] = fmaf(a, w.w, acc[i][3]);
            }
        }
        float4 bb = *(const float4*)(s + OFF_B1 + cg * 4);
        #pragma unroll
        for (int i = 0; i < 8; i++) {
            float4 o;
            o.x = siluf(acc[i][0] + bb.x);
            o.y = siluf(acc[i][1] + bb.y);
            o.z = siluf(acc[i][2] + bb.z);
            o.w = siluf(acc[i][3] + bb.w);
            *(float4*)(s + OFF_H1 + (rg * 8 + i) * 132 + cg * 4) = o;
        }
    }
    __syncthreads();

    // ---- Layer 2: 64x64 = H1(64x128) @ W2(128x64), silu -------------------
    // thread map: rg = tid>>4 (16 groups x 4 rows), cg = tid&15 (16 groups x 4 cols)
    // warp spans rows r, r+4 -> 4*132 % 32 = 16 -> conflict-free.
    {
        const int cg = tid & 15;
        const int rg = tid >> 4;
        float acc[4][4];
        #pragma unroll
        for (int i = 0; i < 4; i++)
            #pragma unroll
            for (int j = 0; j < 4; j++) acc[i][j] = 0.0f;

        const float* wbase = s + OFF_W2 + cg * 4;
        const float* abase = s + OFF_H1 + rg * 4 * 132;

        #pragma unroll 2
        for (int k = 0; k < 128; k++) {
            float4 w = *(const float4*)(wbase + k * 64);
            #pragma unroll
            for (int i = 0; i < 4; i++) {
                float a = abase[i * 132 + k];
                acc[i][0] = fmaf(a, w.x, acc[i][0]);
                acc[i][1] = fmaf(a, w.y, acc[i][1]);
                acc[i][2] = fmaf(a, w.z, acc[i][2]);
                acc[i][3] = fmaf(a, w.w, acc[i][3]);
            }
        }
        float4 bb = *(const float4*)(s + OFF_B2 + cg * 4);
        #pragma unroll
        for (int i = 0; i < 4; i++) {
            float4 o;
            o.x = siluf(acc[i][0] + bb.x);
            o.y = siluf(acc[i][1] + bb.y);
            o.z = siluf(acc[i][2] + bb.z);
            o.w = siluf(acc[i][3] + bb.w);
            *(float4*)(s + OFF_H2 + (rg * 4 + i) * 68 + cg * 4) = o;
        }
    }
    __syncthreads();

    // ---- Layer 3: 64x32 = H2(64x64) @ W3(64x32), silu ---------------------
    // thread map: rg = tid>>4 (16 groups x 4 rows), cg = tid&15 (16 groups x 2 cols)
    // warp spans rows r, r+4 -> 4*68 % 32 = 16 -> conflict-free.
    {
        const int cg = tid & 15;
        const int rg = tid >> 4;
        float acc[4][2];
        #pragma unroll
        for (int i = 0; i < 4; i++) { acc[i][0] = 0.0f; acc[i][1] = 0.0f; }

        const float* wbase = s + OFF_W3 + cg * 2;
        const float* abase = s + OFF_H2 + rg * 4 * 68;

        #pragma unroll 4
        for (int k = 0; k < 64; k++) {
            float2 w = *(const float2*)(wbase + k * 32);
            #pragma unroll
            for (int i = 0; i < 4; i++) {
                float a = abase[i * 68 + k];
                acc[i][0] = fmaf(a, w.x, acc[i][0]);
                acc[i][1] = fmaf(a, w.y, acc[i][1]);
            }
        }
        float2 bb = *(const float2*)(s + OFF_B3 + cg * 2);
        #pragma unroll
        for (int i = 0; i < 4; i++) {
            float2 o;
            o.x = siluf(acc[i][0] + bb.x);
            o.y = siluf(acc[i][1] + bb.y);
            *(float2*)(s + OFF_H3 + (rg * 4 + i) * 36 + cg * 2) = o;
        }
    }
    __syncthreads();

    // ---- Layer 4: raw[b,c] = H3(64x32) . W4(32) + b4 ----------------------
    if (tid < TILE_B) {
        const float* a = s + OFF_H3 + tid * 36;
        float acc = 0.0f;
        #pragma unroll
        for (int h = 0; h < 32; h++) acc = fmaf(a[h], s[OFF_W4 + h], acc);
        acc += b4[c];
        rawOut[(size_t)(b0 + tid) * NCH + c] = acc;
    }
}

// ---------------------------------------------------------------------------
// Kernel 2: coupled fixed-point (5 iters) -> act[b*6 + c]
// ---------------------------------------------------------------------------
__global__ __launch_bounds__(256)
void chambers_couple_kernel(const float* __restrict__ raw,
                            const float* __restrict__ coupling,
                            const float* __restrict__ decay,
                            float* __restrict__ act)
{
    __shared__ float cd[NCH * NCH];   // decay[c] * coupling[c][j] * CF_K
    int t = threadIdx.x;
    if (t < NCH * NCH) {
        int c = t / NCH, j = t % NCH;
        cd[t] = decay[c] * coupling[c * NCH + j] * CF_K;
    }
    __syncthreads();

    int b = blockIdx.x * blockDim.x + t;
    if (b >= BATCH) return;

    float r[NCH], a[NCH];
    #pragma unroll
    for (int c = 0; c < NCH; c++) r[c] = raw[(size_t)b * NCH + c];
    #pragma unroll
    for (int c = 0; c < NCH; c++) a[c] = sigmoidf_fast(r[c]);

    #pragma unroll
    for (int it = 0; it < 5; it++) {
        float d[NCH];
        #pragma unroll
        for (int j = 0; j < NCH; j++) d[j] = 0.0f;
        #pragma unroll
        for (int c = 0; c < NCH; c++) {
            #pragma unroll
            for (int j = 0; j < NCH; j++)
                d[j] = fmaf(a[c], cd[c * NCH + j], d[j]);
        }
        #pragma unroll
        for (int j = 0; j < NCH; j++) a[j] = sigmoidf_fast(r[j] + d[j]);
    }

    #pragma unroll
    for (int c = 0; c < NCH; c++) act[(size_t)b * NCH + c] = a[c];
}

// ---------------------------------------------------------------------------
// Launch
// ---------------------------------------------------------------------------
extern "C" void kernel_launch(void* const* d_in, const int* in_sizes, int n_in,
                              void* d_out, int out_size)
{
    const float* res      = (const float*)d_in[0];
    const float* W1       = (const float*)d_in[1];
    const float* b1       = (const float*)d_in[2];
    const float* W2       = (const float*)d_in[3];
    const float* b2       = (const float*)d_in[4];
    const float* W3       = (const float*)d_in[5];
    const float* b3       = (const float*)d_in[6];
    const float* W4       = (const float*)d_in[7];
    const float* b4       = (const float*)d_in[8];
    const float* coupling = (const float*)d_in[9];
    const float* decay    = (const float*)d_in[10];

    float* out = (float*)d_out;
    float* act = out;                              // [B, 6]
    float* raw = out + (size_t)BATCH * NCH;        // [B, 6]

    cudaFuncSetAttribute(chambers_mlp_kernel,
                         cudaFuncAttributeMaxDynamicSharedMemorySize, SMEM_BYTES);

    dim3 grid(BATCH / TILE_B, NCH);
    chambers_mlp_kernel<<<grid, THREADS, SMEM_BYTES>>>(
        res, W1, b1, W2, b2, W3, b3, W4, b4, raw);

    chambers_couple_kernel<<<(BATCH + 255) / 256, 256>>>(raw, coupling, decay, act);
}

// round 3
// speedup vs baseline: 1.2335x; 1.2335x over previous
#include <cuda_runtime.h>

// ---------------------------------------------------------------------------
// Problem constants
// ---------------------------------------------------------------------------
#define BATCH    131072
#define RES_DIM  100
#define NCH      6
#define CF_K     0.02f
#define TILE_B   64
#define THREADS  256
#define NTILES   (BATCH / TILE_B)      // 2048
#define CTAS_PER_CH 24
#define GRID_MLP (NCH * CTAS_PER_CH)   // 144 persistent CTAs

// ---------------------------------------------------------------------------
// Shared memory layout (float offsets). All offsets multiple of 4 floats.
// Weights stored TRANSPOSED: WnT[col][k], stride padded so stride % 32 == 4
// (conflict-free for lane-major column maps).
// ---------------------------------------------------------------------------
#define OFF_W1T  0        // 128 cols x 100 k  = 12800   (stride 100)
#define OFF_B1   12800    // 128
#define OFF_W2T  12928    // 64 cols x 132     = 8448    (stride 132)
#define OFF_B2   21376    // 64
#define OFF_W3T  21440    // 32 cols x 68      = 2176    (stride 68)
#define OFF_B3   23616    // 32
#define OFF_W4   23648    // 32
#define OFF_RES0 23680    // 64 x 100 = 6400  (double-buffered)
#define OFF_RES1 30080    // 64 x 100 = 6400
#define OFF_H1   36480    // 64 x 128 = 8192
#define OFF_H2   44672    // 64 x 64  = 4096
#define OFF_H3   48768    // 64 x 36  = 2304
#define SMEM_FLOATS 51072
#define SMEM_BYTES  (SMEM_FLOATS * 4)   // 204288 bytes

// ---------------------------------------------------------------------------
// Helpers
// ---------------------------------------------------------------------------
__device__ __forceinline__ float sigmoidf_fast(float x) {
    return 1.0f / (1.0f + __expf(-x));
}
__device__ __forceinline__ float siluf(float x) {
    return x * sigmoidf_fast(x);
}

// Packed fp32x2 FMA: d.lo += a.lo*b.lo ; d.hi += a.hi*b.hi  (one FFMA2 slot)
__device__ __forceinline__ void ffma2(unsigned long long& d,
                                      unsigned long long a,
                                      unsigned long long b) {
    asm("fma.rn.f32x2 %0, %1, %2, %0;" : "+l"(d) : "l"(a), "l"(b));
}

// lo + hi of a packed f32x2 accumulator
__device__ __forceinline__ float accsum(unsigned long long u) {
    float lo, hi;
    asm("mov.b64 {%0, %1}, %2;" : "=f"(lo), "=f"(hi) : "l"(u));
    return lo + hi;
}

__device__ __forceinline__ void cp_async16(void* smem, const void* gmem) {
    unsigned sa = (unsigned)__cvta_generic_to_shared(smem);
    asm volatile("cp.async.ca.shared.global [%0], [%1], 16;" :: "r"(sa), "l"(gmem));
}
__device__ __forceinline__ void cp_commit() {
    asm volatile("cp.async.commit_group;");
}
template <int N>
__device__ __forceinline__ void cp_wait() {
    asm volatile("cp.async.wait_group %0;" :: "n"(N));
}

// ---------------------------------------------------------------------------
// Kernel 1: persistent per-chamber MLP.  144 CTAs; each owns one chamber's
// weights in SMEM and loops over row tiles with cp.async double buffering.
// ---------------------------------------------------------------------------
__global__ __launch_bounds__(THREADS, 1)
void chambers_mlp_kernel(const float* __restrict__ res,
                         const float* __restrict__ W1, const float* __restrict__ b1,
                         const float* __restrict__ W2, const float* __restrict__ b2,
                         const float* __restrict__ W3, const float* __restrict__ b3,
                         const float* __restrict__ W4, const float* __restrict__ b4,
                         float* __restrict__ rawOut)
{
    extern __shared__ float s[];
    const int tid  = threadIdx.x;
    const int c    = blockIdx.x / CTAS_PER_CH;
    const int slot = blockIdx.x % CTAS_PER_CH;
    const int l    = tid & 31;   // lane
    const int w    = tid >> 5;   // warp (8 warps x 8 rows = 64 rows)

    // ---- stage weights once, transposed (coalesced gmem reads) ------------
    {
        const float* W1g = W1 + c * 12800;
        for (int i = tid; i < 12800; i += THREADS) {
            int col = i & 127, k = i >> 7;
            s[OFF_W1T + col * 100 + k] = W1g[k * 128 + col];
        }
        const float* W2g = W2 + c * 8192;
        for (int i = tid; i < 8192; i += THREADS) {
            int col = i & 63, k = i >> 6;
            s[OFF_W2T + col * 132 + k] = W2g[k * 64 + col];
        }
        const float* W3g = W3 + c * 2048;
        for (int i = tid; i < 2048; i += THREADS) {
            int col = i & 31, k = i >> 5;
            s[OFF_W3T + col * 68 + k] = W3g[k * 32 + col];
        }
        if (tid < 128) s[OFF_B1 + tid] = b1[c * 128 + tid];
        if (tid < 64)  s[OFF_B2 + tid] = b2[c * 64 + tid];
        if (tid < 32)  s[OFF_B3 + tid] = b3[c * 32 + tid];
        if (tid < 32)  s[OFF_W4 + tid] = W4[c * 32 + tid];
    }
    const float b4c = b4[c];

    // ---- prologue: async-load first res tile into buffer 0 ----------------
    {
        const float4* src = (const float4*)(res + (size_t)slot * TILE_B * RES_DIM);
        float4* dst = (float4*)(s + OFF_RES0);
        for (int i = tid; i < 1600; i += THREADS) cp_async16(dst + i, src + i);
        cp_commit();
    }

    int p = 0;
    for (int t = slot; t < NTILES; t += CTAS_PER_CH) {
        // prefetch next tile into the other buffer
        int tn = t + CTAS_PER_CH;
        if (tn < NTILES) {
            const float4* src = (const float4*)(res + (size_t)tn * TILE_B * RES_DIM);
            float4* dst = (float4*)(s + (p ? OFF_RES0 : OFF_RES1));
            for (int i = tid; i < 1600; i += THREADS) cp_async16(dst + i, src + i);
            cp_commit();
            cp_wait<1>();
        } else {
            cp_wait<0>();
        }
        __syncthreads();   // current buffer ready (also covers weight staging on iter 0)

        const float* rs = s + (p ? OFF_RES1 : OFF_RES0);

        // ---- Layer 1: res(64x100) @ W1(100x128) -> H1, silu ----------------
        // lanes -> cols (col = l + 32*cc), warp -> 8 rows.  k packed in f32x2.
        {
            unsigned long long acc[8][4];
            #pragma unroll
            for (int i = 0; i < 8; i++)
                #pragma unroll
                for (int cc = 0; cc < 4; cc++) acc[i][cc] = 0ULL;

            const float* abase = rs + w * 8 * RES_DIM;
            const float* wbase = s + OFF_W1T + l * 100;

            #pragma unroll 1
            for (int k0 = 0; k0 < 100; k0 += 4) {
                ulonglong2 av[8];
                #pragma unroll
                for (int i = 0; i < 8; i++)
                    av[i] = *(const ulonglong2*)(abase + i * RES_DIM + k0);
                ulonglong2 wv[4];
                #pragma unroll
                for (int cc = 0; cc < 4; cc++)
                    wv[cc] = *(const ulonglong2*)(wbase + cc * 3200 + k0);
                #pragma unroll
                for (int i = 0; i < 8; i++) {
                    #pragma unroll
                    for (int cc = 0; cc < 4; cc++) {
                        ffma2(acc[i][cc], av[i].x, wv[cc].x);
                        ffma2(acc[i][cc], av[i].y, wv[cc].y);
                    }
                }
            }
            #pragma unroll
            for (int cc = 0; cc < 4; cc++) {
                float bb = s[OFF_B1 + l + 32 * cc];
                #pragma unroll
                for (int i = 0; i < 8; i++) {
                    float v = accsum(acc[i][cc]) + bb;
                    s[OFF_H1 + (w * 8 + i) * 128 + l + 32 * cc] = siluf(v);
                }
            }
        }
        __syncthreads();

        // ---- Layer 2: H1(64x128) @ W2(128x64) -> H2, silu ------------------
        {
            unsigned long long acc[8][2];
            #pragma unroll
            for (int i = 0; i < 8; i++) { acc[i][0] = 0ULL; acc[i][1] = 0ULL; }

            const float* abase = s + OFF_H1 + w * 8 * 128;
            const float* wbase = s + OFF_W2T + l * 132;

            #pragma unroll 1
            for (int k0 = 0; k0 < 128; k0 += 4) {
                ulonglong2 av[8];
                #pragma unroll
                for (int i = 0; i < 8; i++)
                    av[i] = *(const ulonglong2*)(abase + i * 128 + k0);
                ulonglong2 wv[2];
                #pragma unroll
                for (int cc = 0; cc < 2; cc++)
                    wv[cc] = *(const ulonglong2*)(wbase + cc * 32 * 132 + k0);
                #pragma unroll
                for (int i = 0; i < 8; i++) {
                    #pragma unroll
                    for (int cc = 0; cc < 2; cc++) {
                        ffma2(acc[i][cc], av[i].x, wv[cc].x);
                        ffma2(acc[i][cc], av[i].y, wv[cc].y);
                    }
                }
            }
            #pragma unroll
            for (int cc = 0; cc < 2; cc++) {
                float bb = s[OFF_B2 + l + 32 * cc];
                #pragma unroll
                for (int i = 0; i < 8; i++) {
                    float v = accsum(acc[i][cc]) + bb;
                    s[OFF_H2 + (w * 8 + i) * 64 + l + 32 * cc] = siluf(v);
                }
            }
        }
        __syncthreads();

        // ---- Layer 3: H2(64x64) @ W3(64x32) -> H3, silu --------------------
        {
            unsigned long long acc[8];
            #pragma unroll
            for (int i = 0; i < 8; i++) acc[i] = 0ULL;

            const float* abase = s + OFF_H2 + w * 8 * 64;
            const float* wbase = s + OFF_W3T + l * 68;

            #pragma unroll 1
            for (int k0 = 0; k0 < 64; k0 += 4) {
                ulonglong2 wv = *(const ulonglong2*)(wbase + k0);
                ulonglong2 av[8];
                #pragma unroll
                for (int i = 0; i < 8; i++)
                    av[i] = *(const ulonglong2*)(abase + i * 64 + k0);
                #pragma unroll
                for (int i = 0; i < 8; i++) {
                    ffma2(acc[i], av[i].x, wv.x);
                    ffma2(acc[i], av[i].y, wv.y);
                }
            }
            float bb = s[OFF_B3 + l];
            #pragma unroll
            for (int i = 0; i < 8; i++) {
                float v = accsum(acc[i]) + bb;
                s[OFF_H3 + (w * 8 + i) * 36 + l] = siluf(v);
            }
        }
        __syncthreads();

        // ---- Layer 4: raw[b,c] = H3(64x32) . W4(32) + b4 -------------------
        if (tid < TILE_B) {
            const float* a = s + OFF_H3 + tid * 36;
            float accv = b4c;
            #pragma unroll
            for (int h = 0; h < 32; h++) accv = fmaf(a[h], s[OFF_W4 + h], accv);
            rawOut[(size_t)(t * TILE_B + tid) * NCH + c] = accv;
        }
        // top-of-loop __syncthreads covers H3 reuse and res-buffer reuse
        p ^= 1;
    }
}

// ---------------------------------------------------------------------------
// Kernel 2: coupled fixed-point (5 iters) -> act[b*6 + c]
// ---------------------------------------------------------------------------
__global__ __launch_bounds__(256)
void chambers_couple_kernel(const float* __restrict__ raw,
                            const float* __restrict__ coupling,
                            const float* __restrict__ decay,
                            float* __restrict__ act)
{
    __shared__ float cd[NCH * NCH];   // decay[c] * coupling[c][j] * CF_K
    int t = threadIdx.x;
    if (t < NCH * NCH) {
        int c = t / NCH, j = t % NCH;
        cd[t] = decay[c] * coupling[c * NCH + j] * CF_K;
    }
    __syncthreads();

    int b = blockIdx.x * blockDim.x + t;
    if (b >= BATCH) return;

    float r[NCH], a[NCH];
    #pragma unroll
    for (int c = 0; c < NCH; c++) r[c] = raw[(size_t)b * NCH + c];
    #pragma unroll
    for (int c = 0; c < NCH; c++) a[c] = sigmoidf_fast(r[c]);

    #pragma unroll
    for (int it = 0; it < 5; it++) {
        float d[NCH];
        #pragma unroll
        for (int j = 0; j < NCH; j++) d[j] = 0.0f;
        #pragma unroll
        for (int c = 0; c < NCH; c++) {
            #pragma unroll
            for (int j = 0; j < NCH; j++)
                d[j] = fmaf(a[c], cd[c * NCH + j], d[j]);
        }
        #pragma unroll
        for (int j = 0; j < NCH; j++) a[j] = sigmoidf_fast(r[j] + d[j]);
    }

    #pragma unroll
    for (int c = 0; c < NCH; c++) act[(size_t)b * NCH + c] = a[c];
}

// ---------------------------------------------------------------------------
// Launch
// ---------------------------------------------------------------------------
extern "C" void kernel_launch(void* const* d_in, const int* in_sizes, int n_in,
                              void* d_out, int out_size)
{
    const float* res      = (const float*)d_in[0];
    const float* W1       = (const float*)d_in[1];
    const float* b1       = (const float*)d_in[2];
    const float* W2       = (const float*)d_in[3];
    const float* b2       = (const float*)d_in[4];
    const float* W3       = (const float*)d_in[5];
    const float* b3       = (const float*)d_in[6];
    const float* W4       = (const float*)d_in[7];
    const float* b4       = (const float*)d_in[8];
    const float* coupling = (const float*)d_in[9];
    const float* decay    = (const float*)d_in[10];

    float* out = (float*)d_out;
    float* act = out;                              // [B, 6]
    float* raw = out + (size_t)BATCH * NCH;        // [B, 6]

    cudaFuncSetAttribute(chambers_mlp_kernel,
                         cudaFuncAttributeMaxDynamicSharedMemorySize, SMEM_BYTES);

    chambers_mlp_kernel<<<GRID_MLP, THREADS, SMEM_BYTES>>>(
        res, W1, b1, W2, b2, W3, b3, W4, b4, raw);

    chambers_couple_kernel<<<(BATCH + 255) / 256, 256>>>(raw, coupling, decay, act);
}

// round 6
// speedup vs baseline: 2.8920x; 2.3445x over previous
#include <cuda_runtime.h>
#include <cuda_bf16.h>
#include <cstdint>

// ---------------------------------------------------------------------------
// Problem constants
// ---------------------------------------------------------------------------
#define BATCH    131072
#define NCH      6
#define RES_DIM  100
#define CF_K     0.02f
#define TILE_M   128
#define THREADS  256
#define NTILES   (BATCH / TILE_M)     // 1024
#define CTAS_PER_CH 24
#define GRID_MLP (NCH * CTAS_PER_CH)  // 144

// bf16 tile k-stride: 136 elements = 272 bytes (word stride 68 == 4 mod 32 ->
// fragment loads and epilogue stores are bank-conflict-free)
#define KSTR_E   136
#define KSTR_B   272

// ---------------------------------------------------------------------------
// SMEM layout (bytes)
// ---------------------------------------------------------------------------
#define AH_OFF   0                        // A hi : 128 x 136 bf16 = 34816
#define AL_OFF   34816                    // A lo
#define B1H_OFF  69632                    // W1^T hi : 128 x 136
#define B1L_OFF  104448
#define B2H_OFF  139264                   // W2^T hi : 64 x 136 = 17408
#define B2L_OFF  156672
#define B3H_OFF  174080                   // W3^T hi : 32 x 136 = 8704
#define B3L_OFF  182784
#define MISC_B1  191488                   // 128 f32
#define MISC_B2  192000                   // 64 f32
#define MISC_B3  192256                   // 32 f32
#define MISC_W4  192384                   // 32 f32
#define SMEM_BYTES 192512
// L3 epilogue reuses AH region as fp32 H3 scratch, stride 33 floats
#define H3_STRIDE 33

// ---------------------------------------------------------------------------
// Helpers
// ---------------------------------------------------------------------------
__device__ __forceinline__ float sigmoidf_fast(float x) {
    return __fdividef(1.0f, 1.0f + __expf(-x));
}
__device__ __forceinline__ float siluf(float x) { return x * sigmoidf_fast(x); }

__device__ __forceinline__ void split_bf(float x, uint16_t& h, uint16_t& l) {
    __nv_bfloat16 hb = __float2bfloat16(x);
    float r = x - __bfloat162float(hb);
    __nv_bfloat16 lb = __float2bfloat16(r);
    h = *(uint16_t*)&hb;  l = *(uint16_t*)&lb;
}

// one m16n8k16 bf16 MMA, fp32 accum (plain sm_80+ PTX -> HMMA on sm_103a)
__device__ __forceinline__ void mma16816(float c[4],
                                         uint32_t a0, uint32_t a1, uint32_t a2, uint32_t a3,
                                         uint32_t b0, uint32_t b1) {
    asm volatile(
        "mma.sync.aligned.m16n8k16.row.col.f32.bf16.bf16.f32 "
        "{%0,%1,%2,%3}, {%4,%5,%6,%7}, {%8,%9}, {%0,%1,%2,%3};"
        : "+f"(c[0]), "+f"(c[1]), "+f"(c[2]), "+f"(c[3])
        : "r"(a0), "r"(a1), "r"(a2), "r"(a3), "r"(b0), "r"(b1));
}

// ---------------------------------------------------------------------------
// Layer MMA: warp computes [32 x NBLK*8] tile.
//   acc[mb*NBLK+nb][4];  A tiles at aH/aL (hi/lo), B tiles (=W^T) at bH/bL.
//   3 products: Ah*Bh + Ah*Bl + Al*Bh.
// ---------------------------------------------------------------------------
template<int NBLK, int KSTEPS>
__device__ __forceinline__ void layer_mma(const char* smem,
                                          int aH, int aL, int bH, int bL,
                                          int mbase, int nbase, int g, int t,
                                          float (*acc)[4])
{
    #pragma unroll
    for (int i = 0; i < 2 * NBLK; i++)
        #pragma unroll
        for (int j = 0; j < 4; j++) acc[i][j] = 0.0f;

    #pragma unroll
    for (int ks = 0; ks < KSTEPS; ks++) {
        const int kb = ks * 32 + t * 4;      // byte offset of k = ks*16 + 2t
        uint32_t ah[2][4], al[2][4];
        #pragma unroll
        for (int mb = 0; mb < 2; mb++) {
            const char* p = smem + aH + (mbase + mb * 16 + g) * KSTR_B + kb;
            ah[mb][0] = *(const uint32_t*)(p);
            ah[mb][1] = *(const uint32_t*)(p + 8 * KSTR_B);
            ah[mb][2] = *(const uint32_t*)(p + 16);
            ah[mb][3] = *(const uint32_t*)(p + 8 * KSTR_B + 16);
            const char* q = smem + aL + (mbase + mb * 16 + g) * KSTR_B + kb;
            al[mb][0] = *(const uint32_t*)(q);
            al[mb][1] = *(const uint32_t*)(q + 8 * KSTR_B);
            al[mb][2] = *(const uint32_t*)(q + 16);
            al[mb][3] = *(const uint32_t*)(q + 8 * KSTR_B + 16);
        }
        #pragma unroll
        for (int nb = 0; nb < NBLK; nb++) {
            const char* p = smem + bH + (nbase + nb * 8 + g) * KSTR_B + kb;
            uint32_t bh0 = *(const uint32_t*)(p);
            uint32_t bh1 = *(const uint32_t*)(p + 16);
            const char* q = smem + bL + (nbase + nb * 8 + g) * KSTR_B + kb;
            uint32_t bl0 = *(const uint32_t*)(q);
            uint32_t bl1 = *(const uint32_t*)(q + 16);
            #pragma unroll
            for (int mb = 0; mb < 2; mb++) {
                float* c = acc[mb * NBLK + nb];
                mma16816(c, ah[mb][0], ah[mb][1], ah[mb][2], ah[mb][3], bh0, bh1);
                mma16816(c, ah[mb][0], ah[mb][1], ah[mb][2], ah[mb][3], bl0, bl1);
                mma16816(c, al[mb][0], al[mb][1], al[mb][2], al[mb][3], bh0, bh1);
            }
        }
    }
}

// Epilogue: bias + silu, re-split to bf16 hi/lo, store into A tiles.
template<int NBLK>
__device__ __forceinline__ void epi_store_bf(char* smem, int biasOff,
                                             int mbase, int nbase, int g, int t,
                                             float (*acc)[4])
{
    #pragma unroll
    for (int mb = 0; mb < 2; mb++) {
        #pragma unroll
        for (int nb = 0; nb < NBLK; nb++) {
            const float* c = acc[mb * NBLK + nb];
            int col = nbase + nb * 8 + 2 * t;
            float bb0 = *(const float*)(smem + biasOff + col * 4);
            float bb1 = *(const float*)(smem + biasOff + (col + 1) * 4);
            int r0 = mbase + mb * 16 + g;
            // rows r0 (c0,c1) and r0+8 (c2,c3)
            float x0 = siluf(c[0] + bb0), x1 = siluf(c[1] + bb1);
            float y0 = siluf(c[2] + bb0), y1 = siluf(c[3] + bb1);
            uint16_t h0,l0,h1,l1;
            split_bf(x0, h0, l0); split_bf(x1, h1, l1);
            *(uint32_t*)(smem + AH_OFF + r0 * KSTR_B + col * 2) = (uint32_t)h1 << 16 | h0;
            *(uint32_t*)(smem + AL_OFF + r0 * KSTR_B + col * 2) = (uint32_t)l1 << 16 | l0;
            split_bf(y0, h0, l0); split_bf(y1, h1, l1);
            *(uint32_t*)(smem + AH_OFF + (r0+8) * KSTR_B + col * 2) = (uint32_t)h1 << 16 | h0;
            *(uint32_t*)(smem + AL_OFF + (r0+8) * KSTR_B + col * 2) = (uint32_t)l1 << 16 | l0;
        }
    }
}

// ---------------------------------------------------------------------------
// MLP kernel: persistent, HMMA bf16 split-precision
// ---------------------------------------------------------------------------
__global__ __launch_bounds__(THREADS, 1)
void chambers_mlp_hmma(const float* __restrict__ res,
                       const float* __restrict__ W1, const float* __restrict__ b1,
                       const float* __restrict__ W2, const float* __restrict__ b2,
                       const float* __restrict__ W3, const float* __restrict__ b3,
                       const float* __restrict__ W4, const float* __restrict__ b4,
                       float* __restrict__ rawOut)
{
    extern __shared__ char smem[];
    const int tid  = threadIdx.x;
    const int w    = tid >> 5;
    const int lane = tid & 31;
    const int g    = lane >> 2;
    const int t    = lane & 3;
    const int c    = blockIdx.x / CTAS_PER_CH;
    const int slot = blockIdx.x % CTAS_PER_CH;

    // ---- stage weights once: W^T[n][k] bf16 hi/lo, k-stride 136 -----------
    {
        const float* W1g = W1 + c * 12800;
        for (int i = tid; i < 128 * 112; i += THREADS) {
            int n = i / 112, k = i - n * 112;
            float x = (k < RES_DIM) ? W1g[k * 128 + n] : 0.0f;
            uint16_t h, l; split_bf(x, h, l);
            *(uint16_t*)(smem + B1H_OFF + n * KSTR_B + k * 2) = h;
            *(uint16_t*)(smem + B1L_OFF + n * KSTR_B + k * 2) = l;
        }
        const float* W2g = W2 + c * 8192;
        for (int i = tid; i < 64 * 128; i += THREADS) {
            int n = i >> 7, k = i & 127;
            uint16_t h, l; split_bf(W2g[k * 64 + n], h, l);
            *(uint16_t*)(smem + B2H_OFF + n * KSTR_B + k * 2) = h;
            *(uint16_t*)(smem + B2L_OFF + n * KSTR_B + k * 2) = l;
        }
        const float* W3g = W3 + c * 2048;
        for (int i = tid; i < 32 * 64; i += THREADS) {
            int n = i >> 6, k = i & 63;
            uint16_t h, l; split_bf(W3g[k * 32 + n], h, l);
            *(uint16_t*)(smem + B3H_OFF + n * KSTR_B + k * 2) = h;
            *(uint16_t*)(smem + B3L_OFF + n * KSTR_B + k * 2) = l;
        }
        if (tid < 128) *(float*)(smem + MISC_B1 + tid * 4) = b1[c * 128 + tid];
        if (tid < 64)  *(float*)(smem + MISC_B2 + tid * 4) = b2[c * 64 + tid];
        if (tid < 32)  *(float*)(smem + MISC_B3 + tid * 4) = b3[c * 32 + tid];
        if (tid < 32)  *(float*)(smem + MISC_W4 + tid * 4) = W4[c * 32 + tid];
    }
    const float b4c = b4[c];
    __syncthreads();

    const int mbase = (w & 3) * 32;

    for (int tix = slot; tix < NTILES; tix += CTAS_PER_CH) {
        // ---- stage A = res tile fp32 -> bf16 hi/lo, K padded to 112 -------
        {
            const float* rb = res + (size_t)tix * TILE_M * RES_DIM;
            for (int i = tid; i < 128 * 32; i += THREADS) {
                int r = i >> 5, c4 = i & 31;
                if (c4 >= 28) continue;
                float4 v = make_float4(0.f, 0.f, 0.f, 0.f);
                if (c4 < 25) v = *(const float4*)(rb + r * RES_DIM + c4 * 4);
                uint16_t h0,l0,h1,l1,h2,l2,h3,l3;
                split_bf(v.x,h0,l0); split_bf(v.y,h1,l1);
                split_bf(v.z,h2,l2); split_bf(v.w,h3,l3);
                *(uint2*)(smem + AH_OFF + r * KSTR_B + c4 * 8) =
                    make_uint2((uint32_t)h1 << 16 | h0, (uint32_t)h3 << 16 | h2);
                *(uint2*)(smem + AL_OFF + r * KSTR_B + c4 * 8) =
                    make_uint2((uint32_t)l1 << 16 | l0, (uint32_t)l3 << 16 | l2);
            }
        }
        __syncthreads();

        // ---- Layer 1: [128x112] @ W1 -> 128x128, silu ---------------------
        {
            float acc[16][4];
            layer_mma<8, 7>(smem, AH_OFF, AL_OFF, B1H_OFF, B1L_OFF,
                            mbase, (w >> 2) * 64, g, t, acc);
            __syncthreads();
            epi_store_bf<8>(smem, MISC_B1, mbase, (w >> 2) * 64, g, t, acc);
        }
        __syncthreads();

        // ---- Layer 2: [128x128] @ W2 -> 128x64, silu ----------------------
        {
            float acc[8][4];
            layer_mma<4, 8>(smem, AH_OFF, AL_OFF, B2H_OFF, B2L_OFF,
                            mbase, (w >> 2) * 32, g, t, acc);
            __syncthreads();
            epi_store_bf<4>(smem, MISC_B2, mbase, (w >> 2) * 32, g, t, acc);
        }
        __syncthreads();

        // ---- Layer 3: [128x64] @ W3 -> 128x32, silu (fp32 scratch) --------
        {
            float acc[4][4];
            layer_mma<2, 4>(smem, AH_OFF, AL_OFF, B3H_OFF, B3L_OFF,
                            mbase, (w >> 2) * 16, g, t, acc);
            __syncthreads();   // all warps done reading A before fp32 overwrite
            float* h3 = (float*)(smem + AH_OFF);
            const int nbase = (w >> 2) * 16;
            #pragma unroll
            for (int mb = 0; mb < 2; mb++) {
                #pragma unroll
                for (int nb = 0; nb < 2; nb++) {
                    const float* cc = acc[mb * 2 + nb];
                    int col = nbase + nb * 8 + 2 * t;
                    float bb0 = *(const float*)(smem + MISC_B3 + col * 4);
                    float bb1 = *(const float*)(smem + MISC_B3 + (col + 1) * 4);
                    int r0 = mbase + mb * 16 + g;
                    h3[r0 * H3_STRIDE + col]       = siluf(cc[0] + bb0);
                    h3[r0 * H3_STRIDE + col + 1]   = siluf(cc[1] + bb1);
                    h3[(r0+8) * H3_STRIDE + col]   = siluf(cc[2] + bb0);
                    h3[(r0+8) * H3_STRIDE + col+1] = siluf(cc[3] + bb1);
                }
            }
        }
        __syncthreads();

        // ---- Layer 4: dot with W4 -> raw ----------------------------------
        if (tid < TILE_M) {
            const float* h3 = (const float*)(smem + AH_OFF) + tid * H3_STRIDE;
            float acc = b4c;
            #pragma unroll
            for (int h = 0; h < 32; h++)
                acc = fmaf(h3[h], *(const float*)(smem + MISC_W4 + h * 4), acc);
            rawOut[(size_t)(tix * TILE_M + tid) * NCH + c] = acc;
        }
        __syncthreads();   // protect A region before next tile staging
    }
}

// ---------------------------------------------------------------------------
// Coupled fixed-point kernel
// ---------------------------------------------------------------------------
__global__ __launch_bounds__(256)
void chambers_couple_kernel(const float* __restrict__ raw,
                            const float* __restrict__ coupling,
                            const float* __restrict__ decay,
                            float* __restrict__ act)
{
    __shared__ float cd[NCH * NCH];
    int t = threadIdx.x;
    if (t < NCH * NCH) {
        int c = t / NCH, j = t % NCH;
        cd[t] = decay[c] * coupling[c * NCH + j] * CF_K;
    }
    __syncthreads();

    int b = blockIdx.x * blockDim.x + t;
    if (b >= BATCH) return;

    float r[NCH], a[NCH];
    #pragma unroll
    for (int c = 0; c < NCH; c++) r[c] = raw[(size_t)b * NCH + c];
    #pragma unroll
    for (int c = 0; c < NCH; c++) a[c] = sigmoidf_fast(r[c]);

    #pragma unroll
    for (int it = 0; it < 5; it++) {
        float d[NCH];
        #pragma unroll
        for (int j = 0; j < NCH; j++) d[j] = 0.0f;
        #pragma unroll
        for (int c = 0; c < NCH; c++)
            #pragma unroll
            for (int j = 0; j < NCH; j++)
                d[j] = fmaf(a[c], cd[c * NCH + j], d[j]);
        #pragma unroll
        for (int j = 0; j < NCH; j++) a[j] = sigmoidf_fast(r[j] + d[j]);
    }
    #pragma unroll
    for (int c = 0; c < NCH; c++) act[(size_t)b * NCH + c] = a[c];
}

// tiny probe so ncu's -s 5 window lands on the MLP kernel
__global__ void sass_probe_kernel() {}

// ---------------------------------------------------------------------------
// Launch: order [probe, mlp, probe, couple] -> global launch #6 == MLP
// ---------------------------------------------------------------------------
extern "C" void kernel_launch(void* const* d_in, const int* in_sizes, int n_in,
                              void* d_out, int out_size)
{
    const float* res      = (const float*)d_in[0];
    const float* W1       = (const float*)d_in[1];
    const float* b1       = (const float*)d_in[2];
    const float* W2       = (const float*)d_in[3];
    const float* b2       = (const float*)d_in[4];
    const float* W3       = (const float*)d_in[5];
    const float* b3       = (const float*)d_in[6];
    const float* W4       = (const float*)d_in[7];
    const float* b4       = (const float*)d_in[8];
    const float* coupling = (const float*)d_in[9];
    const float* decay    = (const float*)d_in[10];

    float* out = (float*)d_out;
    float* act = out;                          // [B, 6]
    float* raw = out + (size_t)BATCH * NCH;    // [B, 6]

    cudaFuncSetAttribute(chambers_mlp_hmma,
                         cudaFuncAttributeMaxDynamicSharedMemorySize, SMEM_BYTES);

    sass_probe_kernel<<<1, 32>>>();
    chambers_mlp_hmma<<<GRID_MLP, THREADS, SMEM_BYTES>>>(
        res, W1, b1, W2, b2, W3, b3, W4, b4, raw);
    sass_probe_kernel<<<1, 32>>>();
    chambers_couple_kernel<<<(BATCH + 255) / 256, 256>>>(raw, coupling, decay, act);
}